// round 6
// baseline (speedup 1.0000x reference)
#include <cuda_runtime.h>
#include <math.h>

#define NB 4
#define W 512
#define H 512
#define K 256
#define HW (W*H)
#define BORDER 32
#define NLB 1024

// Scratch (device globals; no allocation allowed)
__device__ float  g_stats[NB*(K+1)*8];   // cnt, sum_col, sum_row, sum_inj, sum_t0, sum_t1, sum_rot, sum_sca
__device__ int    g_bbox[NB*K*4];        // src bbox: minr, maxr, minc, maxc
__device__ float  g_coef[NB*K*6];        // affine Hinv: i00,i01,i02,i10,i11,i12
__device__ int    g_dbox[NB*K*4];        // dest bbox: r0,r1,c0,c1 (inclusive); empty if r0>r1
__device__ float  g_proj[NB*HW];
__device__ double g_part[NLB*2];

// ---------------------------------------------------------------------------
__global__ void init_kernel() {
    int gid = blockIdx.x*blockDim.x + threadIdx.x;
    int stride = gridDim.x*blockDim.x;
    for (int i = gid; i < NB*HW; i += stride) g_proj[i] = 0.f;
    for (int i = gid; i < NB*(K+1)*8; i += stride) g_stats[i] = 0.f;
    for (int i = gid; i < NB*K*4; i += stride)
        g_bbox[i] = (i & 1) ? (int)0x80000000 : 0x7fffffff;  // max-slots get INT_MIN, min-slots INT_MAX
}

// ---------------------------------------------------------------------------
// Segment sums + source bboxes. Each block: 1024 consecutive pixels of one batch.
__global__ void stats_kernel(const int*   __restrict__ labels,
                             const float* __restrict__ inj,
                             const float* __restrict__ trs,
                             const float* __restrict__ rot,
                             const float* __restrict__ sca) {
    __shared__ float s_acc[(K+1)*8];
    __shared__ int   s_bb[(K+1)*4];
    int tid = threadIdx.x;
    for (int i = tid; i < (K+1)*8; i += 256) s_acc[i] = 0.f;
    for (int i = tid; i < (K+1)*4; i += 256)
        s_bb[i] = (i & 1) ? (int)0x80000000 : 0x7fffffff;
    __syncthreads();

    int b    = blockIdx.x >> 8;          // HW/1024 = 256 chunks per batch
    int base = (blockIdx.x & 255) * 1024;
    const int*   lb   = labels + b*HW;
    const float* injb = inj + b*HW;
    const float* t0b  = trs + b*2*HW;
    const float* t1b  = t0b + HW;
    const float* rb   = rot + b*HW;
    const float* sb   = sca + b*HW;

#pragma unroll
    for (int i = 0; i < 4; i++) {
        int idx = base + i*256 + tid;
        int lab = lb[idx];
        if (lab >= 1 && lab <= K) {
            int c = idx & (W-1);
            int r = idx >> 9;
            float* a = &s_acc[lab*8];
            atomicAdd(a+0, 1.f);
            atomicAdd(a+1, (float)c);
            atomicAdd(a+2, (float)r);
            atomicAdd(a+3, injb[idx]);
            atomicAdd(a+4, t0b[idx]);
            atomicAdd(a+5, t1b[idx]);
            atomicAdd(a+6, rb[idx]);
            atomicAdd(a+7, sb[idx]);
            int* bb = &s_bb[lab*4];
            atomicMin(bb+0, r);
            atomicMax(bb+1, r);
            atomicMin(bb+2, c);
            atomicMax(bb+3, c);
        }
    }
    __syncthreads();

    for (int lab = 1 + tid; lab <= K; lab += 256) {
        if (s_acc[lab*8] > 0.f) {
            float* g = &g_stats[(b*(K+1)+lab)*8];
#pragma unroll
            for (int j = 0; j < 8; j++) atomicAdd(g+j, s_acc[lab*8+j]);
            int* gb = &g_bbox[(b*K + lab-1)*4];
            atomicMin(gb+0, s_bb[lab*4+0]);
            atomicMax(gb+1, s_bb[lab*4+1]);
            atomicMin(gb+2, s_bb[lab*4+2]);
            atomicMax(gb+3, s_bb[lab*4+3]);
        }
    }
}

// ---------------------------------------------------------------------------
// Per (b,k): means -> H (affine) -> Hinv (analytic) -> dest bbox = H(src bbox)
__global__ void prep_kernel() {
    int idx = blockIdx.x*blockDim.x + threadIdx.x;
    if (idx >= NB*K) return;
    int b = idx / K, k = idx % K;
    const float* st = &g_stats[(b*(K+1) + k + 1)*8];
    float cnt  = st[0];
    float safe = fmaxf(cnt, 1.f);
    float bx = st[1]/safe, by = st[2]/safe, rem = st[3]/safe;
    float ti = st[4]/safe, tj = st[5]/safe;
    float r  = st[6]/safe, s  = st[7]/safe;
    bool valid = (cnt > 0.f) && (rem < 0.5f);
    int* db = &g_dbox[idx*4];
    if (!valid) { db[0]=1; db[1]=0; db[2]=1; db[3]=0; return; }

    float half = (float)(W/2);
    float bxn = (half - bx)/half;
    float byn = (half - by)/half;
    float cR = cosf(r), sn = sinf(r);
    float p = 1.f + s;
    // H = T * Bm_ * S * R * Bm  (bottom row (0,0,1) exactly)
    float h00 = p*cR,  h01 = -p*sn;
    float h02 = p*(cR*bxn - sn*byn) - bxn + ti;
    float h10 = p*sn,  h11 =  p*cR;
    float h12 = p*(sn*bxn + cR*byn) - byn + tj;
    float D   = h00*h11 - h01*h10;
    float i00 =  h11/D, i01 = -h01/D, i02 = (h01*h12 - h11*h02)/D;
    float i10 = -h10/D, i11 =  h00/D, i12 = (h10*h02 - h00*h12)/D;
    float* cf = &g_coef[idx*6];
    cf[0]=i00; cf[1]=i01; cf[2]=i02; cf[3]=i10; cf[4]=i11; cf[5]=i12;

    // dest bbox: image of the (rounding-expanded) src bbox under forward H
    const int* sb = &g_bbox[idx*4];
    float ulo = 2.f*((float)sb[2]-0.5f)/(float)(W-1) - 1.f;
    float uhi = 2.f*((float)sb[3]+0.5f)/(float)(W-1) - 1.f;
    float vlo = 2.f*((float)sb[0]-0.5f)/(float)(H-1) - 1.f;
    float vhi = 2.f*((float)sb[1]+0.5f)/(float)(H-1) - 1.f;
    float xmin=1e30f, xmax=-1e30f, ymin=1e30f, ymax=-1e30f;
#pragma unroll
    for (int ci = 0; ci < 4; ci++) {
        float u = (ci & 1) ? uhi : ulo;
        float v = (ci & 2) ? vhi : vlo;
        float dx = h00*u + h01*v + h02;
        float dy = h10*u + h11*v + h12;
        xmin = fminf(xmin, dx); xmax = fmaxf(xmax, dx);
        ymin = fminf(ymin, dy); ymax = fmaxf(ymax, dy);
    }
    int c0 = max(0,   (int)floorf((xmin+1.f)*(float)(W-1)*0.5f) - 2);
    int c1 = min(W-1, (int)ceilf ((xmax+1.f)*(float)(W-1)*0.5f) + 2);
    int r0 = max(0,   (int)floorf((ymin+1.f)*(float)(H-1)*0.5f) - 2);
    int r1 = min(H-1, (int)ceilf ((ymax+1.f)*(float)(H-1)*0.5f) + 2);
    db[0]=r0; db[1]=r1; db[2]=c0; db[3]=c1;
}

// ---------------------------------------------------------------------------
// One block per (b,k): scan its dest bbox, test exact condition, accumulate proj.
__global__ void scan_kernel(const int* __restrict__ labels) {
    int id = blockIdx.x;
    int b = id / K, k = id % K;
    const int* db = &g_dbox[id*4];
    int r0 = db[0], r1 = db[1], c0 = db[2], c1 = db[3];
    if (r0 > r1 || c0 > c1) return;
    const float* cf = &g_coef[id*6];
    float i00=cf[0], i01=cf[1], i02=cf[2], i10=cf[3], i11=cf[4], i12=cf[5];
    int bw = c1 - c0 + 1;
    int tot = bw * (r1 - r0 + 1);
    const int* lb = labels + b*HW;
    float* pj = g_proj + b*HW;
    const float step = 2.0f/511.0f;
    int match = k + 1;
    for (int t = threadIdx.x; t < tot; t += blockDim.x) {
        int px = c0 + t % bw;
        int py = r0 + t / bw;
        float gx = -1.f + (float)px * step;
        float gy = -1.f + (float)py * step;
        float u = i00*gx + i01*gy + i02;
        float v = i10*gx + i11*gy + i12;
        int ix = __float2int_rn((u + 1.f) * 255.5f);   // round-half-even, matches jnp.round
        int iy = __float2int_rn((v + 1.f) * 255.5f);
        if (ix >= 0 && ix < W && iy >= 0 && iy < H) {
            if (lb[iy*W + ix] == match)
                atomicAdd(&pj[py*W + px], 1.f);   // integer-valued -> exact & deterministic
        }
    }
}

// ---------------------------------------------------------------------------
// Mask write (full image) + cropped-loss partial reduction (double precision).
__global__ void loss_kernel(const float* __restrict__ gti,
                            float* __restrict__ mask_out) {
    double lsq = 0.0, lab = 0.0;
    int gid = blockIdx.x*blockDim.x + threadIdx.x;
    int stride = gridDim.x*blockDim.x;
    for (int i = gid; i < NB*HW; i += stride) {
        float p = g_proj[i];
        mask_out[i] = (p != 0.f) ? 1.f : 0.f;
        int rc = i & (HW-1);
        int r = rc >> 9, c = rc & (W-1);
        if (r >= BORDER && r < H-BORDER && c >= BORDER && c < W-BORDER) {
            float d = p - gti[i];
            lsq += (double)(d*d);
            lab += (double)fabsf(d);
        }
    }
    __shared__ double ssq[256], sab[256];
    ssq[threadIdx.x] = lsq; sab[threadIdx.x] = lab;
    __syncthreads();
    for (int off = 128; off > 0; off >>= 1) {
        if (threadIdx.x < off) {
            ssq[threadIdx.x] += ssq[threadIdx.x+off];
            sab[threadIdx.x] += sab[threadIdx.x+off];
        }
        __syncthreads();
    }
    if (threadIdx.x == 0) {
        g_part[blockIdx.x*2+0] = ssq[0];
        g_part[blockIdx.x*2+1] = sab[0];
    }
}

__global__ void final_kernel(float* __restrict__ out, int write_loss) {
    __shared__ double ssq[256], sab[256];
    double a = 0.0, bs = 0.0;
    for (int i = threadIdx.x; i < NLB; i += 256) {
        a  += g_part[i*2+0];
        bs += g_part[i*2+1];
    }
    ssq[threadIdx.x] = a; sab[threadIdx.x] = bs;
    __syncthreads();
    for (int off = 128; off > 0; off >>= 1) {
        if (threadIdx.x < off) {
            ssq[threadIdx.x] += ssq[threadIdx.x+off];
            sab[threadIdx.x] += sab[threadIdx.x+off];
        }
        __syncthreads();
    }
    if (threadIdx.x == 0 && write_loss) {
        double N = (double)NB * (double)(H-2*BORDER) * (double)(W-2*BORDER);
        out[0] = (float)(ssq[0]/N + sab[0]/N);
    }
}

// ---------------------------------------------------------------------------
// Inputs (metadata order): rgb, mod, gti, seg_inj, trs, rot, sca, labels
extern "C" void kernel_launch(void* const* d_in, const int* in_sizes, int n_in,
                              void* d_out, int out_size) {
    const float* gti    = (const float*)d_in[2];
    const float* inj    = (const float*)d_in[3];
    const float* trs    = (const float*)d_in[4];
    const float* rot    = (const float*)d_in[5];
    const float* sca    = (const float*)d_in[6];
    const int*   labels = (const int*)  d_in[7];
    float* out = (float*)d_out;

    // Output layout: loss scalar first (if present), then (proj != 0) mask as 0/1 floats.
    int extra = out_size - NB*HW;          // expected 1
    float* mask_out = out + (extra > 0 ? extra : 0);
    int write_loss = (extra > 0) ? 1 : 0;

    init_kernel <<<1024, 256>>>();
    stats_kernel<<<1024, 256>>>(labels, inj, trs, rot, sca);
    prep_kernel <<<4, 256>>>();
    scan_kernel <<<NB*K, 256>>>(labels);
    loss_kernel <<<NLB, 256>>>(gti, mask_out);
    final_kernel<<<1, 256>>>(out, write_loss);
}

// round 8
// speedup vs baseline: 2.1405x; 2.1405x over previous
#include <cuda_runtime.h>
#include <math.h>

#define NB 4
#define W 512
#define H 512
#define K 256
#define HW (W*H)
#define BORDER 32
#define CHUNK 4096
#define SBLK (NB*HW/CHUNK)   // 256 stats blocks
#define LBLK 512             // loss blocks

// Scratch (device globals; no allocation allowed)
__device__ float  g_stats[NB*(K+1)*8];   // cnt, sum_col, sum_row, sum_inj, sum_t0, sum_t1, sum_rot, sum_sca
__device__ int    g_bbox[NB*K*4];        // src bbox: minr, maxr, minc, maxc
__device__ float  g_coef[NB*K*6];        // affine Hinv
__device__ int    g_dbox[NB*K*4];        // dest bbox (inclusive); empty if r0>r1
__device__ float  g_proj[NB*HW];
__device__ double g_part[LBLK*2];
__device__ unsigned g_cnt_stats;
__device__ unsigned g_cnt_loss;

// ---------------------------------------------------------------------------
// Tiny init: only small metadata (stats, bbox sentinels, counters).
__global__ void init_kernel() {
    int gid = blockIdx.x*blockDim.x + threadIdx.x;
    int stride = gridDim.x*blockDim.x;
    for (int i = gid; i < NB*(K+1)*8; i += stride) g_stats[i] = 0.f;
    for (int i = gid; i < NB*K*4; i += stride)
        g_bbox[i] = (i & 1) ? (int)0x80000000 : 0x7fffffff;
    if (gid == 0) { g_cnt_stats = 0u; g_cnt_loss = 0u; }
}

// ---------------------------------------------------------------------------
// Segment sums + source bboxes via warp-segmented scan; only run-tail lanes
// issue shared atomics. Last-done block runs prep (means -> H -> Hinv -> dbox).
__global__ void stats_prep_kernel(const int*   __restrict__ labels,
                                  const float* __restrict__ inj,
                                  const float* __restrict__ trs,
                                  const float* __restrict__ rot,
                                  const float* __restrict__ sca) {
    __shared__ float s_acc[(K+1)*8];
    __shared__ int   s_bb[(K+1)*4];
    __shared__ bool  s_last;
    const int tid  = threadIdx.x;
    const int lane = tid & 31;
    for (int i = tid; i < (K+1)*8; i += 256) s_acc[i] = 0.f;
    for (int i = tid; i < (K+1)*4; i += 256)
        s_bb[i] = (i & 1) ? (int)0x80000000 : 0x7fffffff;

    const int base = blockIdx.x * CHUNK;
    // zero this block's slice of g_proj (replaces the old full-image init pass)
#pragma unroll
    for (int j = 0; j < CHUNK/256; j++) g_proj[base + j*256 + tid] = 0.f;
    __syncthreads();

    const unsigned FULL = 0xFFFFFFFFu;
    const int b = base >> 18;                 // CHUNK divides HW -> block in one batch
    const float* t0p = trs + (size_t)b*2*HW;
    const float* t1p = t0p + HW;

#pragma unroll
    for (int j = 0; j < CHUNK/256; j++) {
        int idx = base + j*256 + tid;
        int rc  = idx & (HW-1);
        int lab = labels[idx];
        float p0 = inj[idx];
        float p1 = t0p[rc];
        float p2 = t1p[rc];
        float p3 = rot[idx];
        float p4 = sca[idx];

        // segment structure within the warp (32 consecutive pixels, same row)
        int labp = __shfl_up_sync(FULL, lab, 1);
        bool head = (lane == 0) || (lab != labp);
        unsigned hm = __ballot_sync(FULL, head);
        unsigned le = FULL >> (31 - lane);
        int segstart = 31 - __clz(hm & le);
        bool tail = (lane == 31) || ((hm >> (lane+1)) & 1u);

        // unsegmented inclusive prefix sums (5 fields, 5 steps)
#pragma unroll
        for (int d = 1; d < 32; d <<= 1) {
            float a0 = __shfl_up_sync(FULL, p0, d);
            float a1 = __shfl_up_sync(FULL, p1, d);
            float a2 = __shfl_up_sync(FULL, p2, d);
            float a3 = __shfl_up_sync(FULL, p3, d);
            float a4 = __shfl_up_sync(FULL, p4, d);
            if (lane >= d) { p0 += a0; p1 += a1; p2 += a2; p3 += a3; p4 += a4; }
        }
        int src = (segstart > 0) ? (segstart - 1) : 0;
        float q0 = __shfl_sync(FULL, p0, src);
        float q1 = __shfl_sync(FULL, p1, src);
        float q2 = __shfl_sync(FULL, p2, src);
        float q3 = __shfl_sync(FULL, p3, src);
        float q4 = __shfl_sync(FULL, p4, src);

        if (tail && lab >= 1 && lab <= K) {
            float z = (segstart > 0) ? 1.f : 0.f;
            float s0 = p0 - z*q0, s1 = p1 - z*q1, s2 = p2 - z*q2;
            float s3 = p3 - z*q3, s4 = p4 - z*q4;
            int n   = lane - segstart + 1;
            int r   = rc >> 9;
            int c   = rc & (W-1);
            int cst = c - n + 1;
            float* a = &s_acc[lab*8];
            atomicAdd(a+0, (float)n);
            atomicAdd(a+1, 0.5f * (float)((c + cst) * n));  // arithmetic series, exact
            atomicAdd(a+2, (float)(r * n));
            atomicAdd(a+3, s0);
            atomicAdd(a+4, s1);
            atomicAdd(a+5, s2);
            atomicAdd(a+6, s3);
            atomicAdd(a+7, s4);
            int* bb = &s_bb[lab*4];
            atomicMin(bb+0, r);   atomicMax(bb+1, r);
            atomicMin(bb+2, cst); atomicMax(bb+3, c);
        }
    }
    __syncthreads();

    // flush to global (one label per thread, spread addresses)
    {
        int lab = tid + 1;
        if (lab <= K && s_acc[lab*8] > 0.f) {
            float* g = &g_stats[(b*(K+1) + lab)*8];
#pragma unroll
            for (int t = 0; t < 8; t++) atomicAdd(g + t, s_acc[lab*8 + t]);
            int* gb = &g_bbox[(b*K + lab - 1)*4];
            atomicMin(gb+0, s_bb[lab*4+0]); atomicMax(gb+1, s_bb[lab*4+1]);
            atomicMin(gb+2, s_bb[lab*4+2]); atomicMax(gb+3, s_bb[lab*4+3]);
        }
    }

    // last-done block performs prep
    __threadfence();
    if (tid == 0) {
        unsigned prev = atomicAdd(&g_cnt_stats, 1u);
        s_last = (prev == gridDim.x - 1);
        if (s_last) g_cnt_stats = 0u;      // reset for next graph replay
    }
    __syncthreads();
    if (!s_last) return;
    __threadfence();

    for (int idx2 = tid; idx2 < NB*K; idx2 += 256) {
        int bb2 = idx2 / K, k = idx2 % K;
        const float* st = &g_stats[(bb2*(K+1) + k + 1)*8];
        float cnt  = st[0];
        float safe = fmaxf(cnt, 1.f);
        float bx = st[1]/safe, by = st[2]/safe, rem = st[3]/safe;
        float ti = st[4]/safe, tj = st[5]/safe;
        float r  = st[6]/safe, s  = st[7]/safe;
        bool valid = (cnt > 0.f) && (rem < 0.5f);
        int* db = &g_dbox[idx2*4];
        if (!valid) { db[0]=1; db[1]=0; db[2]=1; db[3]=0; continue; }

        float half = (float)(W/2);
        float bxn = (half - bx)/half;
        float byn = (half - by)/half;
        float cR = cosf(r), sn = sinf(r);
        float p = 1.f + s;
        float h00 = p*cR,  h01 = -p*sn;
        float h02 = p*(cR*bxn - sn*byn) - bxn + ti;
        float h10 = p*sn,  h11 =  p*cR;
        float h12 = p*(sn*bxn + cR*byn) - byn + tj;
        float D   = h00*h11 - h01*h10;
        float i00 =  h11/D, i01 = -h01/D, i02 = (h01*h12 - h11*h02)/D;
        float i10 = -h10/D, i11 =  h00/D, i12 = (h10*h02 - h00*h12)/D;
        float* cf = &g_coef[idx2*6];
        cf[0]=i00; cf[1]=i01; cf[2]=i02; cf[3]=i10; cf[4]=i11; cf[5]=i12;

        const int* sb = &g_bbox[idx2*4];
        float ulo = 2.f*((float)sb[2]-0.5f)/(float)(W-1) - 1.f;
        float uhi = 2.f*((float)sb[3]+0.5f)/(float)(W-1) - 1.f;
        float vlo = 2.f*((float)sb[0]-0.5f)/(float)(H-1) - 1.f;
        float vhi = 2.f*((float)sb[1]+0.5f)/(float)(H-1) - 1.f;
        float xmin=1e30f, xmax=-1e30f, ymin=1e30f, ymax=-1e30f;
#pragma unroll
        for (int ci = 0; ci < 4; ci++) {
            float u = (ci & 1) ? uhi : ulo;
            float v = (ci & 2) ? vhi : vlo;
            float dx = h00*u + h01*v + h02;
            float dy = h10*u + h11*v + h12;
            xmin = fminf(xmin, dx); xmax = fmaxf(xmax, dx);
            ymin = fminf(ymin, dy); ymax = fmaxf(ymax, dy);
        }
        int c0 = max(0,   (int)floorf((xmin+1.f)*(float)(W-1)*0.5f) - 2);
        int c1 = min(W-1, (int)ceilf ((xmax+1.f)*(float)(W-1)*0.5f) + 2);
        int r0 = max(0,   (int)floorf((ymin+1.f)*(float)(H-1)*0.5f) - 2);
        int r1 = min(H-1, (int)ceilf ((ymax+1.f)*(float)(H-1)*0.5f) + 2);
        db[0]=r0; db[1]=r1; db[2]=c0; db[3]=c1;
    }
}

// ---------------------------------------------------------------------------
// One block per (b,k): scan dest bbox, test exact condition, accumulate proj.
// Unroll-2 for independent gather loads in flight.
__global__ void scan_kernel(const int* __restrict__ labels) {
    int id = blockIdx.x;
    int b = id / K, k = id % K;
    const int* db = &g_dbox[id*4];
    int r0 = db[0], r1 = db[1], c0 = db[2], c1 = db[3];
    if (r0 > r1 || c0 > c1) return;
    const float* cf = &g_coef[id*6];
    float i00=cf[0], i01=cf[1], i02=cf[2], i10=cf[3], i11=cf[4], i12=cf[5];
    int bw  = c1 - c0 + 1;
    int tot = bw * (r1 - r0 + 1);
    const int* lb = labels + b*HW;
    float* pj = g_proj + b*HW;
    const float step = 2.0f/511.0f;
    int match = k + 1;

    for (int t = threadIdx.x; t < tot; t += 512) {
        // pixel A
        int pxA = c0 + t % bw;
        int pyA = r0 + t / bw;
        float gxA = -1.f + (float)pxA * step;
        float gyA = -1.f + (float)pyA * step;
        int ixA = __float2int_rn((i00*gxA + i01*gyA + i02 + 1.f) * 255.5f);
        int iyA = __float2int_rn((i10*gxA + i11*gyA + i12 + 1.f) * 255.5f);
        bool okA = (ixA >= 0) & (ixA < W) & (iyA >= 0) & (iyA < H);
        int srcA = okA ? __ldg(&lb[iyA*W + ixA]) : 0;

        // pixel B
        int t2 = t + 256;
        int srcB = 0, pxB = 0, pyB = 0;
        if (t2 < tot) {
            pxB = c0 + t2 % bw;
            pyB = r0 + t2 / bw;
            float gxB = -1.f + (float)pxB * step;
            float gyB = -1.f + (float)pyB * step;
            int ixB = __float2int_rn((i00*gxB + i01*gyB + i02 + 1.f) * 255.5f);
            int iyB = __float2int_rn((i10*gxB + i11*gyB + i12 + 1.f) * 255.5f);
            bool okB = (ixB >= 0) & (ixB < W) & (iyB >= 0) & (iyB < H);
            srcB = okB ? __ldg(&lb[iyB*W + ixB]) : 0;
        }

        if (srcA == match) atomicAdd(&pj[pyA*W + pxA], 1.f);
        if (srcB == match) atomicAdd(&pj[pyB*W + pxB], 1.f);
    }
}

// ---------------------------------------------------------------------------
// Mask write + cropped-loss reduction (double). Last-done block finalizes.
__global__ void loss_final_kernel(const float* __restrict__ gti,
                                  float* __restrict__ mask_out,
                                  float* __restrict__ out, int write_loss) {
    __shared__ double ssq[256], sab[256];
    __shared__ bool s_last;
    int tid = threadIdx.x;
    double lsq = 0.0, labs = 0.0;
    int gid = blockIdx.x*256 + tid;
    for (int i = gid; i < NB*HW; i += LBLK*256) {
        float p = g_proj[i];
        mask_out[i] = (p != 0.f) ? 1.f : 0.f;
        int rc = i & (HW-1);
        int r = rc >> 9, c = rc & (W-1);
        if (r >= BORDER && r < H-BORDER && c >= BORDER && c < W-BORDER) {
            float d = p - gti[i];
            lsq  += (double)(d*d);
            labs += (double)fabsf(d);
        }
    }
    ssq[tid] = lsq; sab[tid] = labs;
    __syncthreads();
    for (int off = 128; off > 0; off >>= 1) {
        if (tid < off) { ssq[tid] += ssq[tid+off]; sab[tid] += sab[tid+off]; }
        __syncthreads();
    }
    if (tid == 0) {
        g_part[blockIdx.x*2+0] = ssq[0];
        g_part[blockIdx.x*2+1] = sab[0];
    }
    __threadfence();
    if (tid == 0) {
        unsigned prev = atomicAdd(&g_cnt_loss, 1u);
        s_last = (prev == gridDim.x - 1);
        if (s_last) g_cnt_loss = 0u;
    }
    __syncthreads();
    if (!s_last) return;
    __threadfence();

    double a  = g_part[2*tid+0]   + g_part[2*(tid+256)+0];
    double bs = g_part[2*tid+1]   + g_part[2*(tid+256)+1];
    ssq[tid] = a; sab[tid] = bs;
    __syncthreads();
    for (int off = 128; off > 0; off >>= 1) {
        if (tid < off) { ssq[tid] += ssq[tid+off]; sab[tid] += sab[tid+off]; }
        __syncthreads();
    }
    if (tid == 0 && write_loss) {
        double N = (double)NB * (double)(H-2*BORDER) * (double)(W-2*BORDER);
        out[0] = (float)(ssq[0]/N + sab[0]/N);
    }
}

// ---------------------------------------------------------------------------
// Inputs (metadata order): rgb, mod, gti, seg_inj, trs, rot, sca, labels
extern "C" void kernel_launch(void* const* d_in, const int* in_sizes, int n_in,
                              void* d_out, int out_size) {
    const float* gti    = (const float*)d_in[2];
    const float* inj    = (const float*)d_in[3];
    const float* trs    = (const float*)d_in[4];
    const float* rot    = (const float*)d_in[5];
    const float* sca    = (const float*)d_in[6];
    const int*   labels = (const int*)  d_in[7];
    float* out = (float*)d_out;

    int extra = out_size - NB*HW;          // expected 1 (loss scalar first)
    float* mask_out = out + (extra > 0 ? extra : 0);
    int write_loss = (extra > 0) ? 1 : 0;

    init_kernel      <<<16, 256>>>();
    stats_prep_kernel<<<SBLK, 256>>>(labels, inj, trs, rot, sca);
    scan_kernel      <<<NB*K, 256>>>(labels);
    loss_final_kernel<<<LBLK, 256>>>(gti, mask_out, out, write_loss);
}

// round 9
// speedup vs baseline: 3.3436x; 1.5621x over previous
#include <cuda_runtime.h>
#include <math.h>

#define NB 4
#define W 512
#define H 512
#define K 256
#define HW (W*H)
#define BORDER 32
#define CHUNK 4096
#define SBLK (NB*HW/CHUNK)   // 256 stats blocks
#define LBLK 1024            // loss blocks (256 thr, 1 float4 each)

// Scratch (device globals; no allocation allowed)
__device__ float  g_stats[NB*(K+1)*8];   // cnt, sum_col, sum_row, sum_inj, sum_t0, sum_t1, sum_rot, sum_sca
__device__ int    g_bbox[NB*K*4];        // src bbox: minr, maxr, minc, maxc
__device__ float  g_coef[NB*K*6];        // affine Hinv
__device__ int    g_dbox[NB*K*4];        // dest bbox (inclusive); empty if r0>r1
__device__ float  g_proj[NB*HW];
__device__ double g_loss_sq, g_loss_ab;
__device__ unsigned g_cnt_stats;
__device__ unsigned g_cnt_loss;

// ---------------------------------------------------------------------------
__global__ void init_kernel() {
    int gid = blockIdx.x*blockDim.x + threadIdx.x;
    int stride = gridDim.x*blockDim.x;
    for (int i = gid; i < NB*(K+1)*8; i += stride) g_stats[i] = 0.f;
    for (int i = gid; i < NB*K*4; i += stride)
        g_bbox[i] = (i & 1) ? (int)0x80000000 : 0x7fffffff;
    if (gid == 0) {
        g_cnt_stats = 0u; g_cnt_loss = 0u;
        g_loss_sq = 0.0;  g_loss_ab = 0.0;
    }
}

// ---------------------------------------------------------------------------
// Segment sums + source bboxes. 4 pixels/thread (float4); warp-segmented scan
// over thread aggregates when each thread's 4 labels are uniform (always true
// for 4-aligned run boundaries); per-pixel shared-atomic fallback otherwise.
// Last-done block runs prep (means -> H -> Hinv -> dest bbox).
__global__ void stats_prep_kernel(const int*   __restrict__ labels,
                                  const float* __restrict__ inj,
                                  const float* __restrict__ trs,
                                  const float* __restrict__ rot,
                                  const float* __restrict__ sca) {
    __shared__ float s_acc[(K+1)*8];
    __shared__ int   s_bb[(K+1)*4];
    __shared__ bool  s_last;
    const int tid  = threadIdx.x;
    const int lane = tid & 31;
    for (int i = tid; i < (K+1)*8; i += 256) s_acc[i] = 0.f;
    for (int i = tid; i < (K+1)*4; i += 256)
        s_bb[i] = (i & 1) ? (int)0x80000000 : 0x7fffffff;

    const int base = blockIdx.x * CHUNK;
    // zero this block's slice of g_proj (float4)
    {
        float4 z4 = make_float4(0.f,0.f,0.f,0.f);
        float4* pz = (float4*)(g_proj + base);
#pragma unroll
        for (int j = 0; j < CHUNK/1024; j++) pz[j*256 + tid] = z4;
    }
    __syncthreads();

    const unsigned FULL = 0xFFFFFFFFu;
    const int b = base >> 18;
    const float* t0p = trs + (size_t)b*2*HW;
    const float* t1p = t0p + HW;

#pragma unroll
    for (int j = 0; j < CHUNK/1024; j++) {
        int idx = base + j*1024 + tid*4;        // first pixel of this thread's group
        int rc  = idx & (HW-1);
        int4   l4 = *(const int4*)  (labels + idx);
        float4 a0 = *(const float4*)(inj + idx);
        float4 a1 = *(const float4*)(t0p + rc);
        float4 a2 = *(const float4*)(t1p + rc);
        float4 a3 = *(const float4*)(rot + idx);
        float4 a4 = *(const float4*)(sca + idx);

        bool uni = (l4.x == l4.y) & (l4.y == l4.z) & (l4.z == l4.w);
        if (__all_sync(FULL, uni)) {
            int lab = l4.x;
            // thread-aggregate sums
            float p0 = (a0.x + a0.y) + (a0.z + a0.w);
            float p1 = (a1.x + a1.y) + (a1.z + a1.w);
            float p2 = (a2.x + a2.y) + (a2.z + a2.w);
            float p3 = (a3.x + a3.y) + (a3.z + a3.w);
            float p4 = (a4.x + a4.y) + (a4.z + a4.w);

            int labp = __shfl_up_sync(FULL, lab, 1);
            bool head = (lane == 0) || (lab != labp);
            unsigned hm = __ballot_sync(FULL, head);
            unsigned le = FULL >> (31 - lane);
            int segstart = 31 - __clz(hm & le);
            bool tail = (lane == 31) || ((hm >> (lane+1)) & 1u);

#pragma unroll
            for (int d = 1; d < 32; d <<= 1) {
                float b0 = __shfl_up_sync(FULL, p0, d);
                float b1 = __shfl_up_sync(FULL, p1, d);
                float b2 = __shfl_up_sync(FULL, p2, d);
                float b3 = __shfl_up_sync(FULL, p3, d);
                float b4 = __shfl_up_sync(FULL, p4, d);
                if (lane >= d) { p0 += b0; p1 += b1; p2 += b2; p3 += b3; p4 += b4; }
            }
            int src = (segstart > 0) ? (segstart - 1) : 0;
            float q0 = __shfl_sync(FULL, p0, src);
            float q1 = __shfl_sync(FULL, p1, src);
            float q2 = __shfl_sync(FULL, p2, src);
            float q3 = __shfl_sync(FULL, p3, src);
            float q4 = __shfl_sync(FULL, p4, src);

            if (tail && lab >= 1 && lab <= K) {
                float z = (segstart > 0) ? 1.f : 0.f;
                float s0 = p0 - z*q0, s1 = p1 - z*q1, s2 = p2 - z*q2;
                float s3 = p3 - z*q3, s4 = p4 - z*q4;
                int n   = (lane - segstart + 1) * 4;      // pixels in run
                int r   = rc >> 9;
                int ce  = (rc & (W-1)) + 3;               // last col of run
                int cst = ce - n + 1;
                float* a = &s_acc[lab*8];
                atomicAdd(a+0, (float)n);
                atomicAdd(a+1, 0.5f * (float)((ce + cst) * n));
                atomicAdd(a+2, (float)(r * n));
                atomicAdd(a+3, s0);
                atomicAdd(a+4, s1);
                atomicAdd(a+5, s2);
                atomicAdd(a+6, s3);
                atomicAdd(a+7, s4);
                int* bb = &s_bb[lab*4];
                atomicMin(bb+0, r);   atomicMax(bb+1, r);
                atomicMin(bb+2, cst); atomicMax(bb+3, ce);
            }
        } else {
            // generic per-pixel fallback (not taken for this dataset's layout)
            int   ls[4] = {l4.x, l4.y, l4.z, l4.w};
            float f0[4] = {a0.x, a0.y, a0.z, a0.w};
            float f1[4] = {a1.x, a1.y, a1.z, a1.w};
            float f2[4] = {a2.x, a2.y, a2.z, a2.w};
            float f3[4] = {a3.x, a3.y, a3.z, a3.w};
            float f4[4] = {a4.x, a4.y, a4.z, a4.w};
#pragma unroll
            for (int e = 0; e < 4; e++) {
                int lab = ls[e];
                if (lab >= 1 && lab <= K) {
                    int rce = rc + e;
                    int r = rce >> 9, c = rce & (W-1);
                    float* a = &s_acc[lab*8];
                    atomicAdd(a+0, 1.f);
                    atomicAdd(a+1, (float)c);
                    atomicAdd(a+2, (float)r);
                    atomicAdd(a+3, f0[e]);
                    atomicAdd(a+4, f1[e]);
                    atomicAdd(a+5, f2[e]);
                    atomicAdd(a+6, f3[e]);
                    atomicAdd(a+7, f4[e]);
                    int* bb = &s_bb[lab*4];
                    atomicMin(bb+0, r); atomicMax(bb+1, r);
                    atomicMin(bb+2, c); atomicMax(bb+3, c);
                }
            }
        }
    }
    __syncthreads();

    // flush to global (one label per thread)
    {
        int lab = tid + 1;
        if (lab <= K && s_acc[lab*8] > 0.f) {
            float* g = &g_stats[(b*(K+1) + lab)*8];
#pragma unroll
            for (int t = 0; t < 8; t++) atomicAdd(g + t, s_acc[lab*8 + t]);
            int* gb = &g_bbox[(b*K + lab - 1)*4];
            atomicMin(gb+0, s_bb[lab*4+0]); atomicMax(gb+1, s_bb[lab*4+1]);
            atomicMin(gb+2, s_bb[lab*4+2]); atomicMax(gb+3, s_bb[lab*4+3]);
        }
    }

    // last-done block performs prep
    __threadfence();
    if (tid == 0) {
        unsigned prev = atomicAdd(&g_cnt_stats, 1u);
        s_last = (prev == gridDim.x - 1);
        if (s_last) g_cnt_stats = 0u;
    }
    __syncthreads();
    if (!s_last) return;
    __threadfence();

    for (int idx2 = tid; idx2 < NB*K; idx2 += 256) {
        int bb2 = idx2 / K, k = idx2 % K;
        const float* st = &g_stats[(bb2*(K+1) + k + 1)*8];
        float cnt  = st[0];
        float safe = fmaxf(cnt, 1.f);
        float bx = st[1]/safe, by = st[2]/safe, rem = st[3]/safe;
        float ti = st[4]/safe, tj = st[5]/safe;
        float r  = st[6]/safe, s  = st[7]/safe;
        bool valid = (cnt > 0.f) && (rem < 0.5f);
        int* db = &g_dbox[idx2*4];
        if (!valid) { db[0]=1; db[1]=0; db[2]=1; db[3]=0; continue; }

        float half = (float)(W/2);
        float bxn = (half - bx)/half;
        float byn = (half - by)/half;
        float cR = cosf(r), sn = sinf(r);
        float p = 1.f + s;
        float h00 = p*cR,  h01 = -p*sn;
        float h02 = p*(cR*bxn - sn*byn) - bxn + ti;
        float h10 = p*sn,  h11 =  p*cR;
        float h12 = p*(sn*bxn + cR*byn) - byn + tj;
        float D   = h00*h11 - h01*h10;
        float i00 =  h11/D, i01 = -h01/D, i02 = (h01*h12 - h11*h02)/D;
        float i10 = -h10/D, i11 =  h00/D, i12 = (h10*h02 - h00*h12)/D;
        float* cf = &g_coef[idx2*6];
        cf[0]=i00; cf[1]=i01; cf[2]=i02; cf[3]=i10; cf[4]=i11; cf[5]=i12;

        const int* sb = &g_bbox[idx2*4];
        float ulo = 2.f*((float)sb[2]-0.5f)/(float)(W-1) - 1.f;
        float uhi = 2.f*((float)sb[3]+0.5f)/(float)(W-1) - 1.f;
        float vlo = 2.f*((float)sb[0]-0.5f)/(float)(H-1) - 1.f;
        float vhi = 2.f*((float)sb[1]+0.5f)/(float)(H-1) - 1.f;
        float xmin=1e30f, xmax=-1e30f, ymin=1e30f, ymax=-1e30f;
#pragma unroll
        for (int ci = 0; ci < 4; ci++) {
            float u = (ci & 1) ? uhi : ulo;
            float v = (ci & 2) ? vhi : vlo;
            float dx = h00*u + h01*v + h02;
            float dy = h10*u + h11*v + h12;
            xmin = fminf(xmin, dx); xmax = fmaxf(xmax, dx);
            ymin = fminf(ymin, dy); ymax = fmaxf(ymax, dy);
        }
        int c0 = max(0,   (int)floorf((xmin+1.f)*(float)(W-1)*0.5f) - 2);
        int c1 = min(W-1, (int)ceilf ((xmax+1.f)*(float)(W-1)*0.5f) + 2);
        int r0 = max(0,   (int)floorf((ymin+1.f)*(float)(H-1)*0.5f) - 2);
        int r1 = min(H-1, (int)ceilf ((ymax+1.f)*(float)(H-1)*0.5f) + 2);
        db[0]=r0; db[1]=r1; db[2]=c0; db[3]=c1;
    }
}

// ---------------------------------------------------------------------------
// One block per (b,k): scan dest bbox, exact test, accumulate proj.
__global__ void scan_kernel(const int* __restrict__ labels) {
    int id = blockIdx.x;
    int b = id / K, k = id % K;
    const int* db = &g_dbox[id*4];
    int r0 = db[0], r1 = db[1], c0 = db[2], c1 = db[3];
    if (r0 > r1 || c0 > c1) return;
    const float* cf = &g_coef[id*6];
    float i00=cf[0], i01=cf[1], i02=cf[2], i10=cf[3], i11=cf[4], i12=cf[5];
    int bw  = c1 - c0 + 1;
    int tot = bw * (r1 - r0 + 1);
    const int* lb = labels + b*HW;
    float* pj = g_proj + b*HW;
    const float step = 2.0f/511.0f;
    int match = k + 1;

    for (int t = threadIdx.x; t < tot; t += 512) {
        int pxA = c0 + t % bw;
        int pyA = r0 + t / bw;
        float gxA = -1.f + (float)pxA * step;
        float gyA = -1.f + (float)pyA * step;
        int ixA = __float2int_rn((i00*gxA + i01*gyA + i02 + 1.f) * 255.5f);
        int iyA = __float2int_rn((i10*gxA + i11*gyA + i12 + 1.f) * 255.5f);
        bool okA = (ixA >= 0) & (ixA < W) & (iyA >= 0) & (iyA < H);
        int srcA = okA ? __ldg(&lb[iyA*W + ixA]) : 0;

        int t2 = t + 256;
        int srcB = 0, pxB = 0, pyB = 0;
        if (t2 < tot) {
            pxB = c0 + t2 % bw;
            pyB = r0 + t2 / bw;
            float gxB = -1.f + (float)pxB * step;
            float gyB = -1.f + (float)pyB * step;
            int ixB = __float2int_rn((i00*gxB + i01*gyB + i02 + 1.f) * 255.5f);
            int iyB = __float2int_rn((i10*gxB + i11*gyB + i12 + 1.f) * 255.5f);
            bool okB = (ixB >= 0) & (ixB < W) & (iyB >= 0) & (iyB < H);
            srcB = okB ? __ldg(&lb[iyB*W + ixB]) : 0;
        }

        if (srcA == match) atomicAdd(&pj[pyA*W + pxA], 1.f);
        if (srcB == match) atomicAdd(&pj[pyB*W + pxB], 1.f);
    }
}

// ---------------------------------------------------------------------------
// Mask write + cropped-loss reduction. float4 loads, one group per thread,
// warp shfl reduce (double), per-block global double atomics; last block writes out.
__global__ void loss_final_kernel(const float* __restrict__ gti,
                                  float* __restrict__ mask_out,
                                  float* __restrict__ out, int write_loss) {
    __shared__ double s_sq[8], s_ab[8];
    __shared__ bool s_last;
    int tid  = threadIdx.x;
    int lane = tid & 31;
    int wid  = tid >> 5;
    int gid  = blockIdx.x*256 + tid;        // one float4 group per thread
    int i    = gid * 4;

    float4 p = ((const float4*)g_proj)[gid];
    float4 g = ((const float4*)gti)[gid];

    mask_out[i+0] = (p.x != 0.f) ? 1.f : 0.f;
    mask_out[i+1] = (p.y != 0.f) ? 1.f : 0.f;
    mask_out[i+2] = (p.z != 0.f) ? 1.f : 0.f;
    mask_out[i+3] = (p.w != 0.f) ? 1.f : 0.f;

    float lsq = 0.f, lab = 0.f;
    int rc = i & (HW-1);
    int r = rc >> 9, c = rc & (W-1);
    if (r >= BORDER && r < H-BORDER) {
        float dx = p.x - g.x, dy = p.y - g.y, dz = p.z - g.z, dw = p.w - g.w;
        if (c+0 >= BORDER && c+0 < W-BORDER) { lsq += dx*dx; lab += fabsf(dx); }
        if (c+1 >= BORDER && c+1 < W-BORDER) { lsq += dy*dy; lab += fabsf(dy); }
        if (c+2 >= BORDER && c+2 < W-BORDER) { lsq += dz*dz; lab += fabsf(dz); }
        if (c+3 >= BORDER && c+3 < W-BORDER) { lsq += dw*dw; lab += fabsf(dw); }
    }
    double dsq = (double)lsq, dab = (double)lab;
#pragma unroll
    for (int off = 16; off > 0; off >>= 1) {
        dsq += __shfl_down_sync(0xFFFFFFFFu, dsq, off);
        dab += __shfl_down_sync(0xFFFFFFFFu, dab, off);
    }
    if (lane == 0) { s_sq[wid] = dsq; s_ab[wid] = dab; }
    __syncthreads();
    if (wid == 0) {
        double a = (lane < 8) ? s_sq[lane] : 0.0;
        double bb = (lane < 8) ? s_ab[lane] : 0.0;
#pragma unroll
        for (int off = 4; off > 0; off >>= 1) {
            a  += __shfl_down_sync(0xFFFFFFFFu, a,  off);
            bb += __shfl_down_sync(0xFFFFFFFFu, bb, off);
        }
        if (lane == 0) {
            atomicAdd(&g_loss_sq, a);
            atomicAdd(&g_loss_ab, bb);
        }
    }
    __threadfence();
    if (tid == 0) {
        unsigned prev = atomicAdd(&g_cnt_loss, 1u);
        s_last = (prev == gridDim.x - 1);
        if (s_last) g_cnt_loss = 0u;
    }
    __syncthreads();
    if (!s_last) return;
    if (tid == 0 && write_loss) {
        __threadfence();
        double N = (double)NB * (double)(H-2*BORDER) * (double)(W-2*BORDER);
        out[0] = (float)(g_loss_sq/N + g_loss_ab/N);
    }
}

// ---------------------------------------------------------------------------
// Inputs (metadata order): rgb, mod, gti, seg_inj, trs, rot, sca, labels
extern "C" void kernel_launch(void* const* d_in, const int* in_sizes, int n_in,
                              void* d_out, int out_size) {
    const float* gti    = (const float*)d_in[2];
    const float* inj    = (const float*)d_in[3];
    const float* trs    = (const float*)d_in[4];
    const float* rot    = (const float*)d_in[5];
    const float* sca    = (const float*)d_in[6];
    const int*   labels = (const int*)  d_in[7];
    float* out = (float*)d_out;

    int extra = out_size - NB*HW;          // expected 1 (loss scalar first)
    float* mask_out = out + (extra > 0 ? extra : 0);
    int write_loss = (extra > 0) ? 1 : 0;

    init_kernel      <<<16, 256>>>();
    stats_prep_kernel<<<SBLK, 256>>>(labels, inj, trs, rot, sca);
    scan_kernel      <<<NB*K, 256>>>(labels);
    loss_final_kernel<<<LBLK, 256>>>(gti, mask_out, out, write_loss);
}